// round 4
// baseline (speedup 1.0000x reference)
#include <cuda_runtime.h>
#include <math.h>

#define NN 100000
#define EE 1600000
#define FF 512
#define HH 256

// ---------------- scratch (static device globals; no allocation) ------------
__device__ float g_B0[(size_t)NN * HH];
__device__ float g_B1[(size_t)NN * HH];
__device__ float g_B2[(size_t)NN * HH];
__device__ int   g_odeg[NN];
__device__ int   g_ideg[NN];
__device__ float g_nsrc[NN];
__device__ float g_ndst[NN];
__device__ float g_psum[HH];
__device__ float g_pmax[HH];
// CSR (in-edges grouped by dst)
__device__ int   g_rowstart[NN + 1];
__device__ int   g_cursor[NN];
__device__ int   g_csr_src[EE];
__device__ int   g_blksum[512];

// ---------------- helpers ---------------------------------------------------
__device__ __forceinline__ void atomicMaxFloat(float* addr, float v) {
    if (v >= 0.0f) atomicMax((int*)addr, __float_as_int(v));
    else           atomicMin((unsigned int*)addr, __float_as_uint(v));
}

__device__ __forceinline__ float leaky(float x) {
    return x > 0.0f ? x : 0.01f * x;
}

__device__ __forceinline__ float4 f4add(float4 a, float4 b) {
    return make_float4(a.x + b.x, a.y + b.y, a.z + b.z, a.w + b.w);
}
__device__ __forceinline__ float4 f4max(float4 a, float4 b) {
    return make_float4(fmaxf(a.x, b.x), fmaxf(a.y, b.y), fmaxf(a.z, b.z), fmaxf(a.w, b.w));
}

// ---------------- small kernels ---------------------------------------------
__global__ void k_zero(float4* p, int n4) {
    int i = blockIdx.x * blockDim.x + threadIdx.x;
    if (i < n4) p[i] = make_float4(0.f, 0.f, 0.f, 0.f);
}

__global__ void k_degree(const int* __restrict__ src, const int* __restrict__ dst) {
    int e = blockIdx.x * blockDim.x + threadIdx.x;
    if (e < EE) {
        atomicAdd(&g_odeg[src[e]], 1);
        atomicAdd(&g_ideg[dst[e]], 1);
    }
}

__global__ void k_norm() {
    int i = blockIdx.x * blockDim.x + threadIdx.x;
    if (i < NN) {
        g_nsrc[i] = rsqrtf(fmaxf((float)g_odeg[i], 1.0f));
        g_ndst[i] = rsqrtf(fmaxf((float)g_ideg[i], 1.0f));
    }
    if (blockIdx.x == 0 && threadIdx.x < HH) {
        g_psum[threadIdx.x] = 0.0f;
        g_pmax[threadIdx.x] = -INFINITY;
    }
}

// ---------------- CSR build: exclusive scan of ideg + cursor fill -----------
__global__ void k_scan1() {
    __shared__ int sh[256];
    int t = threadIdx.x;
    int i = blockIdx.x * 256 + t;
    int v = (i < NN) ? g_ideg[i] : 0;
    sh[t] = v;
    __syncthreads();
    #pragma unroll
    for (int off = 1; off < 256; off <<= 1) {
        int add = (t >= off) ? sh[t - off] : 0;
        __syncthreads();
        sh[t] += add;
        __syncthreads();
    }
    if (i < NN) g_rowstart[i] = sh[t] - v;       // exclusive within block
    if (t == 255) g_blksum[blockIdx.x] = sh[255];
}

__global__ void k_scan2(int nblk) {
    __shared__ int sh[512];
    int t = threadIdx.x;
    int v = (t < nblk) ? g_blksum[t] : 0;
    sh[t] = v;
    __syncthreads();
    #pragma unroll
    for (int off = 1; off < 512; off <<= 1) {
        int add = (t >= off) ? sh[t - off] : 0;
        __syncthreads();
        sh[t] += add;
        __syncthreads();
    }
    if (t < nblk) g_blksum[t] = sh[t] - v;       // exclusive block offsets
}

__global__ void k_scan3() {
    int i = blockIdx.x * blockDim.x + threadIdx.x;
    if (i < NN) {
        g_rowstart[i] += g_blksum[i >> 8];
        g_cursor[i] = 0;
    }
    if (i == 0) g_rowstart[NN] = EE;
}

__global__ void k_csr_fill(const int* __restrict__ src, const int* __restrict__ dst) {
    int e = blockIdx.x * blockDim.x + threadIdx.x;
    if (e < EE) {
        int d = dst[e];
        int pos = atomicAdd(&g_cursor[d], 1);
        g_csr_src[g_rowstart[d] + pos] = src[e];
    }
}

// ---------------- GEMM: C[N,256] = (A[N,K]*norm[row]) @ W[K,256] -------------
template <int K>
__global__ void __launch_bounds__(256)
k_gemm(const float* __restrict__ A, const float* __restrict__ W,
       const float* __restrict__ norm, float* __restrict__ C) {
    __shared__ float As[32][64];
    __shared__ float Bs[32][256];
    const int tid = threadIdx.x;
    const int m0  = blockIdx.x * 64;
    const int tr  = tid >> 5;
    const int tc  = tid & 31;

    float acc[8][8] = {};

    for (int k0 = 0; k0 < K; k0 += 32) {
        #pragma unroll
        for (int i = 0; i < 2; i++) {
            int idx = tid + i * 256;
            int r   = idx >> 3;
            int c   = (idx & 7) << 2;
            int grow = m0 + r;
            float4 v = make_float4(0.f, 0.f, 0.f, 0.f);
            float  nv = 0.f;
            if (grow < NN) {
                v  = *(const float4*)(A + (size_t)grow * K + k0 + c);
                nv = norm[grow];
            }
            As[c + 0][r] = v.x * nv;
            As[c + 1][r] = v.y * nv;
            As[c + 2][r] = v.z * nv;
            As[c + 3][r] = v.w * nv;
        }
        #pragma unroll
        for (int i = 0; i < 8; i++) {
            int idx = tid + i * 256;
            int r   = idx >> 6;
            int c   = (idx & 63) << 2;
            *(float4*)&Bs[r][c] = *(const float4*)(W + (size_t)(k0 + r) * HH + c);
        }
        __syncthreads();

        #pragma unroll
        for (int k = 0; k < 32; k++) {
            float a[8], b[8];
            #pragma unroll
            for (int i = 0; i < 8; i++) a[i] = As[k][tr * 8 + i];
            #pragma unroll
            for (int j = 0; j < 8; j++) b[j] = Bs[k][tc * 8 + j];
            #pragma unroll
            for (int i = 0; i < 8; i++)
                #pragma unroll
                for (int j = 0; j < 8; j++)
                    acc[i][j] = fmaf(a[i], b[j], acc[i][j]);
        }
        __syncthreads();
    }

    #pragma unroll
    for (int i = 0; i < 8; i++) {
        int grow = m0 + tr * 8 + i;
        if (grow < NN) {
            #pragma unroll
            for (int j = 0; j < 8; j += 4) {
                float4 v = make_float4(acc[i][j], acc[i][j + 1], acc[i][j + 2], acc[i][j + 3]);
                *(float4*)(C + (size_t)grow * HH + tc * 8 + j) = v;
            }
        }
    }
}

// ---------------- gather aggregation (CSR), fused activation -----------------
// O[n] = leaky( (sum_{e in in(n)} X[src[e]]) * ndst[n] + bias )
// One warp per node (grid-stride). POOL: also accumulate column sum/max of O.
template <bool POOL>
__global__ void __launch_bounds__(256)
k_gather(const float4* __restrict__ X, float4* __restrict__ O,
         const float* __restrict__ ndst, const float* __restrict__ bias) {
    const int lane   = threadIdx.x & 31;
    const int warp   = (blockIdx.x * blockDim.x + threadIdx.x) >> 5;
    const int nwarps = (gridDim.x * blockDim.x) >> 5;

    float4 bb0 = ((const float4*)bias)[lane];
    float4 bb1 = ((const float4*)bias)[lane + 32];

    float4 ps0, ps1, pm0, pm1;
    if (POOL) {
        ps0 = ps1 = make_float4(0.f, 0.f, 0.f, 0.f);
        pm0 = pm1 = make_float4(-INFINITY, -INFINITY, -INFINITY, -INFINITY);
    }

    for (int n = warp; n < NN; n += nwarps) {
        int beg = g_rowstart[n];
        int end = g_rowstart[n + 1];
        float4 a0 = make_float4(0.f, 0.f, 0.f, 0.f);
        float4 a1 = make_float4(0.f, 0.f, 0.f, 0.f);

        for (int base = beg; base < end; base += 32) {
            int cnt  = min(32, end - base);
            int sidx = (lane < cnt) ? g_csr_src[base + lane] : 0;
            for (int j = 0; j < cnt; j++) {
                int s = __shfl_sync(0xffffffffu, sidx, j);
                const float4* xs = X + (size_t)s * (HH / 4);
                float4 v0 = xs[lane];
                float4 v1 = xs[lane + 32];
                a0 = f4add(a0, v0);
                a1 = f4add(a1, v1);
            }
        }

        float nd = ndst[n];
        float4 o0, o1;
        o0.x = leaky(fmaf(a0.x, nd, bb0.x));
        o0.y = leaky(fmaf(a0.y, nd, bb0.y));
        o0.z = leaky(fmaf(a0.z, nd, bb0.z));
        o0.w = leaky(fmaf(a0.w, nd, bb0.w));
        o1.x = leaky(fmaf(a1.x, nd, bb1.x));
        o1.y = leaky(fmaf(a1.y, nd, bb1.y));
        o1.z = leaky(fmaf(a1.z, nd, bb1.z));
        o1.w = leaky(fmaf(a1.w, nd, bb1.w));

        O[(size_t)n * (HH / 4) + lane]      = o0;
        O[(size_t)n * (HH / 4) + lane + 32] = o1;

        if (POOL) {
            ps0 = f4add(ps0, o0);  ps1 = f4add(ps1, o1);
            pm0 = f4max(pm0, o0);  pm1 = f4max(pm1, o1);
        }
    }

    if (POOL) {
        int c0 = lane * 4;          // columns for o0
        int c1 = 128 + lane * 4;    // columns for o1
        atomicAdd(&g_psum[c0 + 0], ps0.x); atomicAdd(&g_psum[c0 + 1], ps0.y);
        atomicAdd(&g_psum[c0 + 2], ps0.z); atomicAdd(&g_psum[c0 + 3], ps0.w);
        atomicAdd(&g_psum[c1 + 0], ps1.x); atomicAdd(&g_psum[c1 + 1], ps1.y);
        atomicAdd(&g_psum[c1 + 2], ps1.z); atomicAdd(&g_psum[c1 + 3], ps1.w);
        atomicMaxFloat(&g_pmax[c0 + 0], pm0.x); atomicMaxFloat(&g_pmax[c0 + 1], pm0.y);
        atomicMaxFloat(&g_pmax[c0 + 2], pm0.z); atomicMaxFloat(&g_pmax[c0 + 3], pm0.w);
        atomicMaxFloat(&g_pmax[c1 + 0], pm1.x); atomicMaxFloat(&g_pmax[c1 + 1], pm1.y);
        atomicMaxFloat(&g_pmax[c1 + 2], pm1.z); atomicMaxFloat(&g_pmax[c1 + 3], pm1.w);
    }
}

// ---------------- generator head ---------------------------------------------
__global__ void k_final(const float* __restrict__ B, const int* __restrict__ node_index,
                        const float* __restrict__ b2,
                        const float* __restrict__ Wg, const float* __restrict__ bg,
                        const float* __restrict__ eps, float* __restrict__ out) {
    __shared__ float pooled[768];
    __shared__ float red[256];
    int t  = threadIdx.x;
    int ni = *node_index;

    pooled[t]       = g_psum[t];
    pooled[256 + t] = g_pmax[t];
    // B already holds h2 = leaky(agg*ndst+b2) — fused in gather.  Just read row.
    pooled[512 + t] = B[(size_t)ni * HH + t];
    __syncthreads();

    float fdv[4];
    #pragma unroll
    for (int o = 0; o < 4; o++) {
        int k = t + o * 256;
        float acc = bg[k];
        for (int i = 0; i < 768; i++)
            acc = fmaf(pooled[i], Wg[(size_t)i * 1024 + k], acc);
        fdv[o] = acc;
    }
    float mu1 = fdv[0],        mu2 = fdv[1];
    float sg1 = fabsf(fdv[2]), sg2 = fabsf(fdv[3]);
    float e1 = eps[t], e2 = eps[t + 256];
    float fn1 = fmaf(sg1, e1, mu1);
    float fn2 = fmaf(sg2, e2, mu2);

    out[t]              = fn1;  out[t + 256]        = fn2;
    out[512 + t]        = mu1;  out[512 + t + 256]  = mu2;
    out[1024 + t]       = sg1;  out[1024 + t + 256] = sg2;

    const float HALF_LOG_2PI = 0.9189385332046727f;
    float r1 = (fn1 - mu1) / sg1;
    float r2 = (fn2 - mu2) / sg2;
    float lp = (-0.5f * r1 * r1 - logf(sg1) - HALF_LOG_2PI)
             + (-0.5f * r2 * r2 - logf(sg2) - HALF_LOG_2PI);
    red[t] = lp;
    __syncthreads();
    for (int off = 128; off > 0; off >>= 1) {
        if (t < off) red[t] += red[t + off];
        __syncthreads();
    }
    if (t == 0) out[1536] = red[0] / 512.0f;
}

// ---------------- launcher ----------------------------------------------------
extern "C" void kernel_launch(void* const* d_in, const int* in_sizes, int n_in,
                              void* d_out, int out_size) {
    const float* feat = (const float*)d_in[0];
    const int*   src  = (const int*)d_in[1];
    const int*   dst  = (const int*)d_in[2];
    const int*   nidx = (const int*)d_in[3];
    const float* W1   = (const float*)d_in[4];
    const float* b1   = (const float*)d_in[5];
    const float* W2   = (const float*)d_in[6];
    const float* b2   = (const float*)d_in[7];
    const float* Wg   = (const float*)d_in[8];
    const float* bg   = (const float*)d_in[9];
    const float* eps  = (const float*)d_in[10];
    float* out = (float*)d_out;

    void *p0, *p1, *p2, *pod, *pid, *pns, *pnd;
    cudaGetSymbolAddress(&p0, g_B0);
    cudaGetSymbolAddress(&p1, g_B1);
    cudaGetSymbolAddress(&p2, g_B2);
    cudaGetSymbolAddress(&pod, g_odeg);
    cudaGetSymbolAddress(&pid, g_ideg);
    cudaGetSymbolAddress(&pns, g_nsrc);
    cudaGetSymbolAddress(&pnd, g_ndst);
    float* B0 = (float*)p0;
    float* B1 = (float*)p1;
    float* B2 = (float*)p2;
    float* nsrc = (float*)pns;
    float* ndst = (float*)pnd;

    const int DEG_BLKS  = (EE + 255) / 256;
    const int N_BLKS    = (NN + 255) / 256;     // 391
    const int GEMM_BLKS = (NN + 63) / 64;       // 1563
    const int GATH_BLKS = 2048;                  // grid-stride warps

    // degrees + norms
    k_zero<<<(NN / 4 + 255) / 256, 256>>>((float4*)pod, NN / 4);
    k_zero<<<(NN / 4 + 255) / 256, 256>>>((float4*)pid, NN / 4);
    k_degree<<<DEG_BLKS, 256>>>(src, dst);
    k_norm<<<N_BLKS, 256>>>();

    // CSR build (in-edges grouped by dst)
    k_scan1<<<N_BLKS, 256>>>();
    k_scan2<<<1, 512>>>(N_BLKS);
    k_scan3<<<N_BLKS, 256>>>();
    k_csr_fill<<<DEG_BLKS, 256>>>(src, dst);

    // layer 1: B0 = (feat*nsrc)@W1 ; B1 = leaky(gather(B0)*ndst + b1)
    k_gemm<FF><<<GEMM_BLKS, 256>>>(feat, W1, nsrc, B0);
    k_gather<false><<<GATH_BLKS, 256>>>((const float4*)B0, (float4*)B1, ndst, b1);

    // layer 2: B2 = (B1*nsrc)@W2 ; B0 = leaky(gather(B2)*ndst + b2) with fused pooling
    k_gemm<HH><<<GEMM_BLKS, 256>>>(B1, W2, nsrc, B2);
    k_gather<true><<<GATH_BLKS, 256>>>((const float4*)B2, (float4*)B0, ndst, b2);

    // head
    k_final<<<1, 256>>>(B0, nidx, b2, Wg, bg, eps, out);
}

// round 5
// speedup vs baseline: 1.1483x; 1.1483x over previous
#include <cuda_runtime.h>
#include <math.h>
#include <stdint.h>

#define NN 100000
#define EE 1600000
#define FF 512
#define HH 256

// ---------------- scratch (static device globals; no allocation) ------------
__device__ float g_B0[(size_t)NN * HH];
__device__ float g_B1[(size_t)NN * HH];
__device__ float g_B2[(size_t)NN * HH];
__device__ int   g_odeg[NN];
__device__ int   g_ideg[NN];
__device__ float g_nsrc[NN];
__device__ float g_ndst[NN];
__device__ float g_psum[HH];
__device__ float g_pmax[HH];

// ---------------- helpers ---------------------------------------------------
__device__ __forceinline__ void atomicMaxFloat(float* addr, float v) {
    if (v >= 0.0f) atomicMax((int*)addr, __float_as_int(v));
    else           atomicMin((unsigned int*)addr, __float_as_uint(v));
}

__device__ __forceinline__ float leaky(float x) {
    return x > 0.0f ? x : 0.01f * x;
}

__device__ __forceinline__ uint32_t f2tf(float x) {
    uint32_t u;
    asm("cvt.rna.tf32.f32 %0, %1;" : "=r"(u) : "f"(x));
    return u;
}

__device__ __forceinline__ void mma_tf32(float* d, const uint32_t* a, const uint32_t* b) {
    asm volatile(
        "mma.sync.aligned.m16n8k8.row.col.f32.tf32.tf32.f32 "
        "{%0,%1,%2,%3}, {%4,%5,%6,%7}, {%8,%9}, {%0,%1,%2,%3};\n"
        : "+f"(d[0]), "+f"(d[1]), "+f"(d[2]), "+f"(d[3])
        : "r"(a[0]), "r"(a[1]), "r"(a[2]), "r"(a[3]), "r"(b[0]), "r"(b[1]));
}

// ---------------- small kernels ---------------------------------------------
__global__ void k_zero(float4* p, int n4) {
    int i = blockIdx.x * blockDim.x + threadIdx.x;
    if (i < n4) p[i] = make_float4(0.f, 0.f, 0.f, 0.f);
}

__global__ void k_degree(const int* __restrict__ src, const int* __restrict__ dst) {
    int e = blockIdx.x * blockDim.x + threadIdx.x;
    if (e < EE) {
        atomicAdd(&g_odeg[src[e]], 1);
        atomicAdd(&g_ideg[dst[e]], 1);
    }
}

__global__ void k_norm() {
    int i = blockIdx.x * blockDim.x + threadIdx.x;
    if (i < NN) {
        g_nsrc[i] = rsqrtf(fmaxf((float)g_odeg[i], 1.0f));
        g_ndst[i] = rsqrtf(fmaxf((float)g_ideg[i], 1.0f));
    }
    if (blockIdx.x == 0 && threadIdx.x < HH) {
        g_psum[threadIdx.x] = 0.0f;
        g_pmax[threadIdx.x] = -INFINITY;
    }
}

// ---------------- tensor-core GEMM (3xTF32) ----------------------------------
// C[N,256] = (A[N,K] * norm[row]) @ W[K,256]
// BM=128, BN=128, BK=16, 256 threads = 8 warps, warp tile 32(m)x64(n).
template <int K>
__global__ void __launch_bounds__(256, 2)
k_gemm_tc(const float* __restrict__ A, const float* __restrict__ W,
          const float* __restrict__ norm, float* __restrict__ C) {
    __shared__ uint32_t Ah[16][132];
    __shared__ uint32_t Al[16][132];
    __shared__ uint32_t Bh[16][132];
    __shared__ uint32_t Bl[16][132];

    const int tid  = threadIdx.x;
    const int lane = tid & 31;
    const int wid  = tid >> 5;
    const int wm   = wid >> 1;       // 0..3
    const int wn   = wid & 1;        // 0..1
    const int m0   = blockIdx.y * 128;
    const int n0   = blockIdx.x * 128;

    // --- loader geometry (fixed per thread across k-iterations) ---
    const int a_r0 = tid >> 2;             // 0..63
    const int a_r1 = a_r0 + 64;            // 64..127
    const int a_c  = (tid & 3) << 2;       // 0,4,8,12
    const int b_r0 = tid >> 5;             // 0..7
    const int b_r1 = b_r0 + 8;             // 8..15
    const int b_c  = (tid & 31) << 2;      // 0..124

    const float nrm0 = (m0 + a_r0 < NN) ? norm[m0 + a_r0] : 0.f;
    const float nrm1 = (m0 + a_r1 < NN) ? norm[m0 + a_r1] : 0.f;

    float acc[2][8][4];
    #pragma unroll
    for (int mt = 0; mt < 2; mt++)
        #pragma unroll
        for (int nt = 0; nt < 8; nt++)
            #pragma unroll
            for (int i = 0; i < 4; i++) acc[mt][nt][i] = 0.f;

    float4 pa0, pa1, pb0, pb1;

    // ---- tile load helpers (via regs) ----
    #define LOAD_TILE(kt)                                                        \
        {                                                                        \
            int kbase = (kt) * 16;                                               \
            pa0 = (m0 + a_r0 < NN)                                               \
                ? *(const float4*)(A + (size_t)(m0 + a_r0) * K + kbase + a_c)    \
                : make_float4(0.f, 0.f, 0.f, 0.f);                               \
            pa1 = (m0 + a_r1 < NN)                                               \
                ? *(const float4*)(A + (size_t)(m0 + a_r1) * K + kbase + a_c)    \
                : make_float4(0.f, 0.f, 0.f, 0.f);                               \
            pb0 = *(const float4*)(W + (size_t)(kbase + b_r0) * HH + n0 + b_c);  \
            pb1 = *(const float4*)(W + (size_t)(kbase + b_r1) * HH + n0 + b_c);  \
        }

    #define STORE_TILE()                                                         \
        {                                                                        \
            float av[8] = {pa0.x * nrm0, pa0.y * nrm0, pa0.z * nrm0,             \
                           pa0.w * nrm0, pa1.x * nrm1, pa1.y * nrm1,             \
                           pa1.z * nrm1, pa1.w * nrm1};                          \
            _Pragma("unroll")                                                    \
            for (int j = 0; j < 4; j++) {                                        \
                uint32_t h0 = f2tf(av[j]);                                       \
                Ah[a_c + j][a_r0] = h0;                                          \
                Al[a_c + j][a_r0] = f2tf(av[j] - __uint_as_float(h0));           \
                uint32_t h1 = f2tf(av[4 + j]);                                   \
                Ah[a_c + j][a_r1] = h1;                                          \
                Al[a_c + j][a_r1] = f2tf(av[4 + j] - __uint_as_float(h1));       \
            }                                                                    \
            float bv[8] = {pb0.x, pb0.y, pb0.z, pb0.w, pb1.x, pb1.y, pb1.z, pb1.w}; \
            _Pragma("unroll")                                                    \
            for (int j = 0; j < 4; j++) {                                        \
                uint32_t h0 = f2tf(bv[j]);                                       \
                Bh[b_r0][b_c + j] = h0;                                          \
                Bl[b_r0][b_c + j] = f2tf(bv[j] - __uint_as_float(h0));           \
                uint32_t h1 = f2tf(bv[4 + j]);                                   \
                Bh[b_r1][b_c + j] = h1;                                          \
                Bl[b_r1][b_c + j] = f2tf(bv[4 + j] - __uint_as_float(h1));       \
            }                                                                    \
        }

    constexpr int KT = K / 16;

    LOAD_TILE(0);
    STORE_TILE();
    __syncthreads();

    for (int kt = 0; kt < KT; kt++) {
        if (kt + 1 < KT) LOAD_TILE(kt + 1);

        #pragma unroll
        for (int kk = 0; kk < 2; kk++) {
            const int colA = kk * 8 + (lane & 3);
            const int rowA = wm * 32 + (lane >> 2);
            const int rowB = kk * 8 + (lane & 3);
            const int colB = wn * 64 + (lane >> 2);

            uint32_t ah[2][4];
            #pragma unroll
            for (int mt = 0; mt < 2; mt++) {
                int r = rowA + mt * 16;
                ah[mt][0] = Ah[colA][r];
                ah[mt][1] = Ah[colA][r + 8];
                ah[mt][2] = Ah[colA + 4][r];
                ah[mt][3] = Ah[colA + 4][r + 8];
            }
            uint32_t bh[8][2];
            #pragma unroll
            for (int nt = 0; nt < 8; nt++) {
                bh[nt][0] = Bh[rowB][colB + nt * 8];
                bh[nt][1] = Bh[rowB + 4][colB + nt * 8];
            }
            // pass 1: Ah * Bh
            #pragma unroll
            for (int mt = 0; mt < 2; mt++)
                #pragma unroll
                for (int nt = 0; nt < 8; nt++)
                    mma_tf32(acc[mt][nt], ah[mt], bh[nt]);

            // pass 2: Ah * Bl
            uint32_t bl[8][2];
            #pragma unroll
            for (int nt = 0; nt < 8; nt++) {
                bl[nt][0] = Bl[rowB][colB + nt * 8];
                bl[nt][1] = Bl[rowB + 4][colB + nt * 8];
            }
            #pragma unroll
            for (int mt = 0; mt < 2; mt++)
                #pragma unroll
                for (int nt = 0; nt < 8; nt++)
                    mma_tf32(acc[mt][nt], ah[mt], bl[nt]);

            // pass 3: Al * Bh
            uint32_t al[2][4];
            #pragma unroll
            for (int mt = 0; mt < 2; mt++) {
                int r = rowA + mt * 16;
                al[mt][0] = Al[colA][r];
                al[mt][1] = Al[colA][r + 8];
                al[mt][2] = Al[colA + 4][r];
                al[mt][3] = Al[colA + 4][r + 8];
            }
            #pragma unroll
            for (int mt = 0; mt < 2; mt++)
                #pragma unroll
                for (int nt = 0; nt < 8; nt++)
                    mma_tf32(acc[mt][nt], al[mt], bh[nt]);
        }

        __syncthreads();
        if (kt + 1 < KT) {
            STORE_TILE();
            __syncthreads();
        }
    }

    // epilogue
    #pragma unroll
    for (int mt = 0; mt < 2; mt++) {
        #pragma unroll
        for (int nt = 0; nt < 8; nt++) {
            int row = m0 + wm * 32 + mt * 16 + (lane >> 2);
            int col = n0 + wn * 64 + nt * 8 + (lane & 3) * 2;
            if (row < NN)
                *(float2*)(C + (size_t)row * HH + col) =
                    make_float2(acc[mt][nt][0], acc[mt][nt][1]);
            if (row + 8 < NN)
                *(float2*)(C + (size_t)(row + 8) * HH + col) =
                    make_float2(acc[mt][nt][2], acc[mt][nt][3]);
        }
    }
    #undef LOAD_TILE
    #undef STORE_TILE
}

// ---------------- atomic scatter: A[dst[e]] += X[src[e]] ---------------------
__global__ void k_scatter(const float4* __restrict__ X, float4* __restrict__ A,
                          const int* __restrict__ src, const int* __restrict__ dst) {
    int w    = (blockIdx.x * blockDim.x + threadIdx.x) >> 5;
    int lane = threadIdx.x & 31;
    if (w >= EE) return;
    int s = __ldg(src + w);
    int d = __ldg(dst + w);
    const float4* xs = X + (size_t)s * (HH / 4);
    float4*       ad = A + (size_t)d * (HH / 4);
    float4 v0 = xs[lane];
    float4 v1 = xs[lane + 32];
    atomicAdd(ad + lane, v0);
    atomicAdd(ad + lane + 32, v1);
}

// O = leaky(A * ndst[row] + b[col])
__global__ void k_act(const float4* __restrict__ A, const float* __restrict__ ndst,
                      const float* __restrict__ b, float4* __restrict__ O) {
    int i = blockIdx.x * blockDim.x + threadIdx.x;
    if (i >= NN * (HH / 4)) return;
    int row = i >> 6;
    int c4  = (i & 63) << 2;
    float  nd = ndst[row];
    float4 v  = A[i];
    float4 bb = *(const float4*)(b + c4);
    v.x = leaky(fmaf(v.x, nd, bb.x));
    v.y = leaky(fmaf(v.y, nd, bb.y));
    v.z = leaky(fmaf(v.z, nd, bb.z));
    v.w = leaky(fmaf(v.w, nd, bb.w));
    O[i] = v;
}

// column-wise sum + max of h2 = leaky(B*ndst+b2), computed on the fly
__global__ void k_pool(const float* __restrict__ B, const float* __restrict__ ndst,
                       const float* __restrict__ b2) {
    int col = threadIdx.x;
    int n0  = blockIdx.x * 256;
    float bb = b2[col];
    float s = 0.0f, m = -INFINITY;
    int nend = min(n0 + 256, NN);
    for (int r = n0; r < nend; r++) {
        float v = leaky(fmaf(B[(size_t)r * HH + col], ndst[r], bb));
        s += v;
        m = fmaxf(m, v);
    }
    atomicAdd(&g_psum[col], s);
    atomicMaxFloat(&g_pmax[col], m);
}

// generator head
__global__ void k_final(const float* __restrict__ B, const int* __restrict__ node_index,
                        const float* __restrict__ b2,
                        const float* __restrict__ Wg, const float* __restrict__ bg,
                        const float* __restrict__ eps, float* __restrict__ out) {
    __shared__ float pooled[768];
    __shared__ float red[256];
    int t  = threadIdx.x;
    int ni = *node_index;

    pooled[t]       = g_psum[t];
    pooled[256 + t] = g_pmax[t];
    float nd = g_ndst[ni];
    pooled[512 + t] = leaky(fmaf(B[(size_t)ni * HH + t], nd, b2[t]));
    __syncthreads();

    float fdv[4];
    #pragma unroll
    for (int o = 0; o < 4; o++) {
        int k = t + o * 256;
        float acc = bg[k];
        for (int i = 0; i < 768; i++)
            acc = fmaf(pooled[i], Wg[(size_t)i * 1024 + k], acc);
        fdv[o] = acc;
    }
    float mu1 = fdv[0],        mu2 = fdv[1];
    float sg1 = fabsf(fdv[2]), sg2 = fabsf(fdv[3]);
    float e1 = eps[t], e2 = eps[t + 256];
    float fn1 = fmaf(sg1, e1, mu1);
    float fn2 = fmaf(sg2, e2, mu2);

    out[t]              = fn1;  out[t + 256]        = fn2;
    out[512 + t]        = mu1;  out[512 + t + 256]  = mu2;
    out[1024 + t]       = sg1;  out[1024 + t + 256] = sg2;

    const float HALF_LOG_2PI = 0.9189385332046727f;
    float r1 = (fn1 - mu1) / sg1;
    float r2 = (fn2 - mu2) / sg2;
    float lp = (-0.5f * r1 * r1 - logf(sg1) - HALF_LOG_2PI)
             + (-0.5f * r2 * r2 - logf(sg2) - HALF_LOG_2PI);
    red[t] = lp;
    __syncthreads();
    for (int off = 128; off > 0; off >>= 1) {
        if (t < off) red[t] += red[t + off];
        __syncthreads();
    }
    if (t == 0) out[1536] = red[0] / 512.0f;
}

// ---------------- launcher ----------------------------------------------------
extern "C" void kernel_launch(void* const* d_in, const int* in_sizes, int n_in,
                              void* d_out, int out_size) {
    const float* feat = (const float*)d_in[0];
    const int*   src  = (const int*)d_in[1];
    const int*   dst  = (const int*)d_in[2];
    const int*   nidx = (const int*)d_in[3];
    const float* W1   = (const float*)d_in[4];
    const float* b1   = (const float*)d_in[5];
    const float* W2   = (const float*)d_in[6];
    const float* b2   = (const float*)d_in[7];
    const float* Wg   = (const float*)d_in[8];
    const float* bg   = (const float*)d_in[9];
    const float* eps  = (const float*)d_in[10];
    float* out = (float*)d_out;

    void *p0, *p1, *p2, *pod, *pid, *pns, *pnd;
    cudaGetSymbolAddress(&p0, g_B0);
    cudaGetSymbolAddress(&p1, g_B1);
    cudaGetSymbolAddress(&p2, g_B2);
    cudaGetSymbolAddress(&pod, g_odeg);
    cudaGetSymbolAddress(&pid, g_ideg);
    cudaGetSymbolAddress(&pns, g_nsrc);
    cudaGetSymbolAddress(&pnd, g_ndst);
    float* B0 = (float*)p0;
    float* B1 = (float*)p1;
    float* B2 = (float*)p2;
    float* nsrc = (float*)pns;
    float* ndst = (float*)pnd;

    const int NH4       = NN * (HH / 4);        // 6,400,000 float4s
    const int Z_BLKS    = NH4 / 256;            // 25000
    const int DEG_BLKS  = (EE + 255) / 256;
    const int N_BLKS    = (NN + 255) / 256;     // 391
    const dim3 GEMM_GRID(2, (NN + 127) / 128);  // (n-tiles, m-tiles) = (2, 782)
    const int SCAT_BLKS = EE / 8;               // 200000

    // degrees + norms
    k_zero<<<(NN / 4 + 255) / 256, 256>>>((float4*)pod, NN / 4);
    k_zero<<<(NN / 4 + 255) / 256, 256>>>((float4*)pid, NN / 4);
    k_degree<<<DEG_BLKS, 256>>>(src, dst);
    k_norm<<<N_BLKS, 256>>>();

    // layer 1: B0 = (feat*nsrc)@W1 ; B1 = scatter(B0) ; B0 = leaky(B1*ndst+b1)
    k_gemm_tc<FF><<<GEMM_GRID, 256>>>(feat, W1, nsrc, B0);
    k_zero<<<Z_BLKS, 256>>>((float4*)B1, NH4);
    k_scatter<<<SCAT_BLKS, 256>>>((const float4*)B0, (float4*)B1, src, dst);
    k_act<<<Z_BLKS, 256>>>((const float4*)B1, ndst, b1, (float4*)B0);

    // layer 2: B2 = (B0*nsrc)@W2 ; B0 = scatter(B2)
    k_gemm_tc<HH><<<GEMM_GRID, 256>>>(B0, W2, nsrc, B2);
    k_zero<<<Z_BLKS, 256>>>((float4*)B0, NH4);
    k_scatter<<<SCAT_BLKS, 256>>>((const float4*)B2, (float4*)B0, src, dst);

    // pooling + head
    k_pool<<<N_BLKS, 256>>>(B0, ndst, b2);
    k_final<<<1, 256>>>(B0, nidx, b2, Wg, bg, eps, out);
}

// round 6
// speedup vs baseline: 1.4969x; 1.3036x over previous
#include <cuda_runtime.h>
#include <math.h>
#include <stdint.h>

#define NN 100000
#define EE 1600000
#define FF 512
#define HH 256

// ---------------- scratch (static device globals; no allocation) ------------
__device__ float g_B0[(size_t)NN * HH];
__device__ float g_B1[(size_t)NN * HH];
__device__ float g_B2[(size_t)NN * HH];
__device__ int   g_odeg[NN];
__device__ int   g_ideg[NN];
__device__ float g_nsrc[NN];
__device__ float g_ndst[NN];
__device__ float g_psum[HH];
__device__ float g_pmax[HH];
// CSR (in-edges grouped by dst)
__device__ int   g_rowstart[NN + 1];
__device__ int   g_cursor[NN];
__device__ int   g_csr_src[EE];
__device__ int   g_blksum[512];

// ---------------- helpers ---------------------------------------------------
__device__ __forceinline__ void atomicMaxFloat(float* addr, float v) {
    if (v >= 0.0f) atomicMax((int*)addr, __float_as_int(v));
    else           atomicMin((unsigned int*)addr, __float_as_uint(v));
}
__device__ __forceinline__ void atomicMaxFloatSh(float* addr, float v) {
    if (v >= 0.0f) atomicMax((int*)addr, __float_as_int(v));
    else           atomicMin((unsigned int*)addr, __float_as_uint(v));
}

__device__ __forceinline__ float leaky(float x) {
    return x > 0.0f ? x : 0.01f * x;
}

__device__ __forceinline__ float4 f4add(float4 a, float4 b) {
    return make_float4(a.x + b.x, a.y + b.y, a.z + b.z, a.w + b.w);
}

__device__ __forceinline__ uint32_t f2tf(float x) {
    uint32_t u;
    asm("cvt.rna.tf32.f32 %0, %1;" : "=r"(u) : "f"(x));
    return u;
}

__device__ __forceinline__ void mma_tf32(float* d, const uint32_t* a, const uint32_t* b) {
    asm volatile(
        "mma.sync.aligned.m16n8k8.row.col.f32.tf32.tf32.f32 "
        "{%0,%1,%2,%3}, {%4,%5,%6,%7}, {%8,%9}, {%0,%1,%2,%3};\n"
        : "+f"(d[0]), "+f"(d[1]), "+f"(d[2]), "+f"(d[3])
        : "r"(a[0]), "r"(a[1]), "r"(a[2]), "r"(a[3]), "r"(b[0]), "r"(b[1]));
}

// ---------------- small kernels ---------------------------------------------
__global__ void k_zero(float4* p, int n4) {
    int i = blockIdx.x * blockDim.x + threadIdx.x;
    if (i < n4) p[i] = make_float4(0.f, 0.f, 0.f, 0.f);
}

__global__ void k_degree(const int* __restrict__ src, const int* __restrict__ dst) {
    int e = blockIdx.x * blockDim.x + threadIdx.x;
    if (e < EE) {
        atomicAdd(&g_odeg[src[e]], 1);
        atomicAdd(&g_ideg[dst[e]], 1);
    }
}

__global__ void k_norm() {
    int i = blockIdx.x * blockDim.x + threadIdx.x;
    if (i < NN) {
        g_nsrc[i] = rsqrtf(fmaxf((float)g_odeg[i], 1.0f));
        g_ndst[i] = rsqrtf(fmaxf((float)g_ideg[i], 1.0f));
    }
    if (blockIdx.x == 0 && threadIdx.x < HH) {
        g_psum[threadIdx.x] = 0.0f;
        g_pmax[threadIdx.x] = -INFINITY;
    }
}

// ---------------- CSR build ---------------------------------------------------
__global__ void k_scan1() {
    __shared__ int sh[256];
    int t = threadIdx.x;
    int i = blockIdx.x * 256 + t;
    int v = (i < NN) ? g_ideg[i] : 0;
    sh[t] = v;
    __syncthreads();
    #pragma unroll
    for (int off = 1; off < 256; off <<= 1) {
        int add = (t >= off) ? sh[t - off] : 0;
        __syncthreads();
        sh[t] += add;
        __syncthreads();
    }
    if (i < NN) g_rowstart[i] = sh[t] - v;
    if (t == 255) g_blksum[blockIdx.x] = sh[255];
}

__global__ void k_scan2(int nblk) {
    __shared__ int sh[512];
    int t = threadIdx.x;
    int v = (t < nblk) ? g_blksum[t] : 0;
    sh[t] = v;
    __syncthreads();
    #pragma unroll
    for (int off = 1; off < 512; off <<= 1) {
        int add = (t >= off) ? sh[t - off] : 0;
        __syncthreads();
        sh[t] += add;
        __syncthreads();
    }
    if (t < nblk) g_blksum[t] = sh[t] - v;
}

__global__ void k_scan3() {
    int i = blockIdx.x * blockDim.x + threadIdx.x;
    if (i < NN) {
        g_rowstart[i] += g_blksum[i >> 8];
        g_cursor[i] = 0;
    }
    if (i == 0) g_rowstart[NN] = EE;
}

__global__ void k_csr_fill(const int* __restrict__ src, const int* __restrict__ dst) {
    int e = blockIdx.x * blockDim.x + threadIdx.x;
    if (e < EE) {
        int d = dst[e];
        int pos = atomicAdd(&g_cursor[d], 1);
        g_csr_src[g_rowstart[d] + pos] = src[e];
    }
}

// ---------------- tensor-core GEMM (3xTF32) ----------------------------------
template <int K>
__global__ void __launch_bounds__(256, 2)
k_gemm_tc(const float* __restrict__ A, const float* __restrict__ W,
          const float* __restrict__ norm, float* __restrict__ C) {
    __shared__ uint32_t Ah[16][132];
    __shared__ uint32_t Al[16][132];
    __shared__ uint32_t Bh[16][132];
    __shared__ uint32_t Bl[16][132];

    const int tid  = threadIdx.x;
    const int lane = tid & 31;
    const int wid  = tid >> 5;
    const int wm   = wid >> 1;
    const int wn   = wid & 1;
    const int m0   = blockIdx.y * 128;
    const int n0   = blockIdx.x * 128;

    const int a_r0 = tid >> 2;
    const int a_r1 = a_r0 + 64;
    const int a_c  = (tid & 3) << 2;
    const int b_r0 = tid >> 5;
    const int b_r1 = b_r0 + 8;
    const int b_c  = (tid & 31) << 2;

    const float nrm0 = (m0 + a_r0 < NN) ? norm[m0 + a_r0] : 0.f;
    const float nrm1 = (m0 + a_r1 < NN) ? norm[m0 + a_r1] : 0.f;

    float acc[2][8][4];
    #pragma unroll
    for (int mt = 0; mt < 2; mt++)
        #pragma unroll
        for (int nt = 0; nt < 8; nt++)
            #pragma unroll
            for (int i = 0; i < 4; i++) acc[mt][nt][i] = 0.f;

    float4 pa0, pa1, pb0, pb1;

    #define LOAD_TILE(kt)                                                        \
        {                                                                        \
            int kbase = (kt) * 16;                                               \
            pa0 = (m0 + a_r0 < NN)                                               \
                ? *(const float4*)(A + (size_t)(m0 + a_r0) * K + kbase + a_c)    \
                : make_float4(0.f, 0.f, 0.f, 0.f);                               \
            pa1 = (m0 + a_r1 < NN)                                               \
                ? *(const float4*)(A + (size_t)(m0 + a_r1) * K + kbase + a_c)    \
                : make_float4(0.f, 0.f, 0.f, 0.f);                               \
            pb0 = *(const float4*)(W + (size_t)(kbase + b_r0) * HH + n0 + b_c);  \
            pb1 = *(const float4*)(W + (size_t)(kbase + b_r1) * HH + n0 + b_c);  \
        }

    #define STORE_TILE()                                                         \
        {                                                                        \
            float av[8] = {pa0.x * nrm0, pa0.y * nrm0, pa0.z * nrm0,             \
                           pa0.w * nrm0, pa1.x * nrm1, pa1.y * nrm1,             \
                           pa1.z * nrm1, pa1.w * nrm1};                          \
            _Pragma("unroll")                                                    \
            for (int j = 0; j < 4; j++) {                                        \
                uint32_t h0 = f2tf(av[j]);                                       \
                Ah[a_c + j][a_r0] = h0;                                          \
                Al[a_c + j][a_r0] = f2tf(av[j] - __uint_as_float(h0));           \
                uint32_t h1 = f2tf(av[4 + j]);                                   \
                Ah[a_c + j][a_r1] = h1;                                          \
                Al[a_c + j][a_r1] = f2tf(av[4 + j] - __uint_as_float(h1));       \
            }                                                                    \
            float bv[8] = {pb0.x, pb0.y, pb0.z, pb0.w, pb1.x, pb1.y, pb1.z, pb1.w}; \
            _Pragma("unroll")                                                    \
            for (int j = 0; j < 4; j++) {                                        \
                uint32_t h0 = f2tf(bv[j]);                                       \
                Bh[b_r0][b_c + j] = h0;                                          \
                Bl[b_r0][b_c + j] = f2tf(bv[j] - __uint_as_float(h0));           \
                uint32_t h1 = f2tf(bv[4 + j]);                                   \
                Bh[b_r1][b_c + j] = h1;                                          \
                Bl[b_r1][b_c + j] = f2tf(bv[4 + j] - __uint_as_float(h1));       \
            }                                                                    \
        }

    constexpr int KT = K / 16;

    LOAD_TILE(0);
    STORE_TILE();
    __syncthreads();

    for (int kt = 0; kt < KT; kt++) {
        if (kt + 1 < KT) LOAD_TILE(kt + 1);

        #pragma unroll
        for (int kk = 0; kk < 2; kk++) {
            const int colA = kk * 8 + (lane & 3);
            const int rowA = wm * 32 + (lane >> 2);
            const int rowB = kk * 8 + (lane & 3);
            const int colB = wn * 64 + (lane >> 2);

            uint32_t ah[2][4];
            #pragma unroll
            for (int mt = 0; mt < 2; mt++) {
                int r = rowA + mt * 16;
                ah[mt][0] = Ah[colA][r];
                ah[mt][1] = Ah[colA][r + 8];
                ah[mt][2] = Ah[colA + 4][r];
                ah[mt][3] = Ah[colA + 4][r + 8];
            }
            uint32_t bh[8][2];
            #pragma unroll
            for (int nt = 0; nt < 8; nt++) {
                bh[nt][0] = Bh[rowB][colB + nt * 8];
                bh[nt][1] = Bh[rowB + 4][colB + nt * 8];
            }
            #pragma unroll
            for (int mt = 0; mt < 2; mt++)
                #pragma unroll
                for (int nt = 0; nt < 8; nt++)
                    mma_tf32(acc[mt][nt], ah[mt], bh[nt]);

            uint32_t bl[8][2];
            #pragma unroll
            for (int nt = 0; nt < 8; nt++) {
                bl[nt][0] = Bl[rowB][colB + nt * 8];
                bl[nt][1] = Bl[rowB + 4][colB + nt * 8];
            }
            #pragma unroll
            for (int mt = 0; mt < 2; mt++)
                #pragma unroll
                for (int nt = 0; nt < 8; nt++)
                    mma_tf32(acc[mt][nt], ah[mt], bl[nt]);

            uint32_t al[2][4];
            #pragma unroll
            for (int mt = 0; mt < 2; mt++) {
                int r = rowA + mt * 16;
                al[mt][0] = Al[colA][r];
                al[mt][1] = Al[colA][r + 8];
                al[mt][2] = Al[colA + 4][r];
                al[mt][3] = Al[colA + 4][r + 8];
            }
            #pragma unroll
            for (int mt = 0; mt < 2; mt++)
                #pragma unroll
                for (int nt = 0; nt < 8; nt++)
                    mma_tf32(acc[mt][nt], al[mt], bh[nt]);
        }

        __syncthreads();
        if (kt + 1 < KT) {
            STORE_TILE();
            __syncthreads();
        }
    }

    #pragma unroll
    for (int mt = 0; mt < 2; mt++) {
        #pragma unroll
        for (int nt = 0; nt < 8; nt++) {
            int row = m0 + wm * 32 + mt * 16 + (lane >> 2);
            int col = n0 + wn * 64 + nt * 8 + (lane & 3) * 2;
            if (row < NN)
                *(float2*)(C + (size_t)row * HH + col) =
                    make_float2(acc[mt][nt][0], acc[mt][nt][1]);
            if (row + 8 < NN)
                *(float2*)(C + (size_t)(row + 8) * HH + col) =
                    make_float2(acc[mt][nt][2], acc[mt][nt][3]);
        }
    }
    #undef LOAD_TILE
    #undef STORE_TILE
}

// ---------------- CSR gather, warp per node, 4-edge unrolled -----------------
// O[n] = leaky( (sum_{e in in(n)} X[src[e]]) * ndst[n] + bias )
template <bool POOL>
__global__ void __launch_bounds__(256)
k_gather(const float4* __restrict__ X, float4* __restrict__ O,
         const float* __restrict__ ndst, const float* __restrict__ bias) {
    __shared__ float s_sum[HH];
    __shared__ float s_max[HH];

    const int lane = threadIdx.x & 31;
    const int n    = (blockIdx.x * blockDim.x + threadIdx.x) >> 5;

    if (POOL) {
        s_sum[threadIdx.x] = 0.0f;
        s_max[threadIdx.x] = -INFINITY;
        __syncthreads();
    }

    float4 o0, o1;
    bool valid = (n < NN);
    if (valid) {
        const int beg = g_rowstart[n];
        const int end = g_rowstart[n + 1];
        float4 a0 = make_float4(0.f, 0.f, 0.f, 0.f);
        float4 a1 = make_float4(0.f, 0.f, 0.f, 0.f);

        int e = beg;
        for (; e + 4 <= end; e += 4) {
            // uniform broadcast loads of 4 indices (independent)
            int s0 = __ldg(&g_csr_src[e + 0]);
            int s1 = __ldg(&g_csr_src[e + 1]);
            int s2 = __ldg(&g_csr_src[e + 2]);
            int s3 = __ldg(&g_csr_src[e + 3]);
            const float4* x0 = X + (size_t)s0 * (HH / 4);
            const float4* x1 = X + (size_t)s1 * (HH / 4);
            const float4* x2 = X + (size_t)s2 * (HH / 4);
            const float4* x3 = X + (size_t)s3 * (HH / 4);
            // 8 independent LDG.128 in flight
            float4 v00 = x0[lane];      float4 v01 = x0[lane + 32];
            float4 v10 = x1[lane];      float4 v11 = x1[lane + 32];
            float4 v20 = x2[lane];      float4 v21 = x2[lane + 32];
            float4 v30 = x3[lane];      float4 v31 = x3[lane + 32];
            a0 = f4add(a0, f4add(f4add(v00, v10), f4add(v20, v30)));
            a1 = f4add(a1, f4add(f4add(v01, v11), f4add(v21, v31)));
        }
        for (; e < end; e++) {
            int s = __ldg(&g_csr_src[e]);
            const float4* xs = X + (size_t)s * (HH / 4);
            a0 = f4add(a0, xs[lane]);
            a1 = f4add(a1, xs[lane + 32]);
        }

        const float nd = ndst[n];
        float4 bb0 = ((const float4*)bias)[lane];
        float4 bb1 = ((const float4*)bias)[lane + 32];
        o0.x = leaky(fmaf(a0.x, nd, bb0.x));
        o0.y = leaky(fmaf(a0.y, nd, bb0.y));
        o0.z = leaky(fmaf(a0.z, nd, bb0.z));
        o0.w = leaky(fmaf(a0.w, nd, bb0.w));
        o1.x = leaky(fmaf(a1.x, nd, bb1.x));
        o1.y = leaky(fmaf(a1.y, nd, bb1.y));
        o1.z = leaky(fmaf(a1.z, nd, bb1.z));
        o1.w = leaky(fmaf(a1.w, nd, bb1.w));

        O[(size_t)n * (HH / 4) + lane]      = o0;
        O[(size_t)n * (HH / 4) + lane + 32] = o1;
    }

    if (POOL) {
        if (valid) {
            const int c0 = lane * 4;
            const int c1 = 128 + lane * 4;
            atomicAdd(&s_sum[c0 + 0], o0.x); atomicAdd(&s_sum[c0 + 1], o0.y);
            atomicAdd(&s_sum[c0 + 2], o0.z); atomicAdd(&s_sum[c0 + 3], o0.w);
            atomicAdd(&s_sum[c1 + 0], o1.x); atomicAdd(&s_sum[c1 + 1], o1.y);
            atomicAdd(&s_sum[c1 + 2], o1.z); atomicAdd(&s_sum[c1 + 3], o1.w);
            atomicMaxFloatSh(&s_max[c0 + 0], o0.x); atomicMaxFloatSh(&s_max[c0 + 1], o0.y);
            atomicMaxFloatSh(&s_max[c0 + 2], o0.z); atomicMaxFloatSh(&s_max[c0 + 3], o0.w);
            atomicMaxFloatSh(&s_max[c1 + 0], o1.x); atomicMaxFloatSh(&s_max[c1 + 1], o1.y);
            atomicMaxFloatSh(&s_max[c1 + 2], o1.z); atomicMaxFloatSh(&s_max[c1 + 3], o1.w);
        }
        __syncthreads();
        // one thread per column -> one global atomic pair per block
        atomicAdd(&g_psum[threadIdx.x], s_sum[threadIdx.x]);
        atomicMaxFloat(&g_pmax[threadIdx.x], s_max[threadIdx.x]);
    }
}

// ---------------- generator head ---------------------------------------------
__global__ void k_final(const float* __restrict__ B, const int* __restrict__ node_index,
                        const float* __restrict__ b2,
                        const float* __restrict__ Wg, const float* __restrict__ bg,
                        const float* __restrict__ eps, float* __restrict__ out) {
    __shared__ float pooled[768];
    __shared__ float red[256];
    int t  = threadIdx.x;
    int ni = *node_index;

    pooled[t]       = g_psum[t];
    pooled[256 + t] = g_pmax[t];
    // B already holds h2 (activation fused into gather)
    pooled[512 + t] = B[(size_t)ni * HH + t];
    __syncthreads();

    float fdv[4];
    #pragma unroll
    for (int o = 0; o < 4; o++) {
        int k = t + o * 256;
        float acc = bg[k];
        for (int i = 0; i < 768; i++)
            acc = fmaf(pooled[i], Wg[(size_t)i * 1024 + k], acc);
        fdv[o] = acc;
    }
    float mu1 = fdv[0],        mu2 = fdv[1];
    float sg1 = fabsf(fdv[2]), sg2 = fabsf(fdv[3]);
    float e1 = eps[t], e2 = eps[t + 256];
    float fn1 = fmaf(sg1, e1, mu1);
    float fn2 = fmaf(sg2, e2, mu2);

    out[t]              = fn1;  out[t + 256]        = fn2;
    out[512 + t]        = mu1;  out[512 + t + 256]  = mu2;
    out[1024 + t]       = sg1;  out[1024 + t + 256] = sg2;

    const float HALF_LOG_2PI = 0.9189385332046727f;
    float r1 = (fn1 - mu1) / sg1;
    float r2 = (fn2 - mu2) / sg2;
    float lp = (-0.5f * r1 * r1 - logf(sg1) - HALF_LOG_2PI)
             + (-0.5f * r2 * r2 - logf(sg2) - HALF_LOG_2PI);
    red[t] = lp;
    __syncthreads();
    for (int off = 128; off > 0; off >>= 1) {
        if (t < off) red[t] += red[t + off];
        __syncthreads();
    }
    if (t == 0) out[1536] = red[0] / 512.0f;
}

// ---------------- launcher ----------------------------------------------------
extern "C" void kernel_launch(void* const* d_in, const int* in_sizes, int n_in,
                              void* d_out, int out_size) {
    const float* feat = (const float*)d_in[0];
    const int*   src  = (const int*)d_in[1];
    const int*   dst  = (const int*)d_in[2];
    const int*   nidx = (const int*)d_in[3];
    const float* W1   = (const float*)d_in[4];
    const float* b1   = (const float*)d_in[5];
    const float* W2   = (const float*)d_in[6];
    const float* b2   = (const float*)d_in[7];
    const float* Wg   = (const float*)d_in[8];
    const float* bg   = (const float*)d_in[9];
    const float* eps  = (const float*)d_in[10];
    float* out = (float*)d_out;

    void *p0, *p1, *p2, *pod, *pid, *pns, *pnd;
    cudaGetSymbolAddress(&p0, g_B0);
    cudaGetSymbolAddress(&p1, g_B1);
    cudaGetSymbolAddress(&p2, g_B2);
    cudaGetSymbolAddress(&pod, g_odeg);
    cudaGetSymbolAddress(&pid, g_ideg);
    cudaGetSymbolAddress(&pns, g_nsrc);
    cudaGetSymbolAddress(&pnd, g_ndst);
    float* B0 = (float*)p0;
    float* B1 = (float*)p1;
    float* B2 = (float*)p2;
    float* nsrc = (float*)pns;
    float* ndst = (float*)pnd;

    const int DEG_BLKS  = (EE + 255) / 256;
    const int N_BLKS    = (NN + 255) / 256;      // 391
    const dim3 GEMM_GRID(2, (NN + 127) / 128);   // 782 m-tiles x 2 n-tiles
    const int GATH_BLKS = (NN + 7) / 8;          // one warp per node, 8 warps/block

    // degrees + norms
    k_zero<<<(NN / 4 + 255) / 256, 256>>>((float4*)pod, NN / 4);
    k_zero<<<(NN / 4 + 255) / 256, 256>>>((float4*)pid, NN / 4);
    k_degree<<<DEG_BLKS, 256>>>(src, dst);
    k_norm<<<N_BLKS, 256>>>();

    // CSR build (in-edges grouped by dst)
    k_scan1<<<N_BLKS, 256>>>();
    k_scan2<<<1, 512>>>(N_BLKS);
    k_scan3<<<N_BLKS, 256>>>();
    k_csr_fill<<<DEG_BLKS, 256>>>(src, dst);

    // layer 1: B0 = (feat*nsrc)@W1 ; B1 = leaky(gather(B0)*ndst + b1)
    k_gemm_tc<FF><<<GEMM_GRID, 256>>>(feat, W1, nsrc, B0);
    k_gather<false><<<GATH_BLKS, 256>>>((const float4*)B0, (float4*)B1, ndst, b1);

    // layer 2: B2 = (B1*nsrc)@W2 ; B0 = leaky(gather(B2)*ndst + b2), fused pooling
    k_gemm_tc<HH><<<GEMM_GRID, 256>>>(B1, W2, nsrc, B2);
    k_gather<true><<<GATH_BLKS, 256>>>((const float4*)B2, (float4*)B0, ndst, b2);

    // head
    k_final<<<1, 256>>>(B0, nidx, b2, Wg, bg, eps, out);
}